// round 3
// baseline (speedup 1.0000x reference)
#include <cuda_runtime.h>
#include <cstdint>

#define B_    4096
#define FIN   64
#define NK    512
#define FOUT  256
#define TB    32
#define NTHR  512
#define XP    68            // x / center staging pitch (floats)
#define PR    516           // rbf row pitch: rows 4 apart differ by 64B mod 512 -> conflict-free
#define WP    68            // W chunk pitch: cols 4 apart differ by 64B mod 512 -> conflict-free
#define KC    64            // k per W chunk
#define NCH   (NK/KC)       // 8 chunks

__device__ float g_cc[NK];          // ||c_k||^2
__device__ float g_s2[NK];          // exp(2*log_shape_k)

// -------- smem layout (float offsets) --------
#define SM_RBF  0                         // rbf[32][PR]  (row-major, k contiguous)
#define SM_X    (SM_RBF + TB*PR)          // x[32][XP]
#define SM_U    (SM_X + TB*XP)            // union: phase1 centers 2*64*XP | phase3 W 2*256*WP
#define U_SZ    (2*FOUT*WP)
#define SM_CC   (SM_U + U_SZ)
#define SM_S2   (SM_CC + NK)
#define SM_XX   (SM_S2 + NK)
#define SM_INV  (SM_XX + TB)
#define SM_TOT  (SM_INV + TB)
#define SMEM_BYTES (SM_TOT * 4)           // ~218 KB

#define FMA2(a,b,c) asm("fma.rn.f32x2 %0, %1, %2, %0;" : "+l"(a) : "l"(b), "l"(c))

__device__ __forceinline__ void cp16(uint32_t dst, const void* src) {
    asm volatile("cp.async.ca.shared.global [%0], [%1], 16;" :: "r"(dst), "l"(src));
}

// -------- prep: ||c||^2 and exp(2*ls) --------
__global__ void prep_centers(const float* __restrict__ centers,
                             const float* __restrict__ ls) {
    int kb = blockIdx.x * 32;
    int warp = threadIdx.x >> 5, lane = threadIdx.x & 31;
    #pragma unroll
    for (int c = warp; c < 32; c += 8) {
        int k = kb + c;
        float v0 = centers[k * FIN + lane];
        float v1 = centers[k * FIN + 32 + lane];
        float s = fmaf(v0, v0, v1 * v1);
        #pragma unroll
        for (int off = 16; off; off >>= 1) s += __shfl_xor_sync(0xffffffffu, s, off);
        if (lane == 0) g_cc[k] = s;
    }
    if (threadIdx.x < 32) g_s2[kb + threadIdx.x] = __expf(2.f * ls[kb + threadIdx.x]);
}

// -------- fused main kernel --------
__global__ __launch_bounds__(NTHR, 1)
void rbf_main(const float* __restrict__ x,
              const float* __restrict__ centers,
              const float* __restrict__ W,
              float* __restrict__ out) {
    extern __shared__ float sm[];
    float* s_rbf = sm + SM_RBF;
    float* s_x   = sm + SM_X;
    float* s_cc  = sm + SM_CC;
    float* s_s2  = sm + SM_S2;
    float* s_xx  = sm + SM_XX;
    float* s_inv = sm + SM_INV;

    const int tid  = threadIdx.x;
    const int lane = tid & 31;
    const int warp = tid >> 5;
    const int b0   = blockIdx.x * TB;
    const uint32_t smem_u = (uint32_t)__cvta_generic_to_shared(sm);

    // ---- stage x tile (one float4/thread) + per-k constants ----
    {
        const float4* x4 = (const float4*)(x + (size_t)b0 * FIN);
        int r = tid >> 4, c = tid & 15;
        *(float4*)&s_x[r * XP + c * 4] = x4[r * 16 + c];
        s_cc[tid] = g_cc[tid];
        s_s2[tid] = g_s2[tid];
    }

    // ---- cp.async: center pass 0 into union buf 0 ----
    {
        const float4* src = (const float4*)centers;
        #pragma unroll
        for (int i = tid; i < 1024; i += NTHR) {
            int r = i >> 4, c = i & 15;
            cp16(smem_u + (SM_U + r * XP + c * 4) * 4, src + i);
        }
        asm volatile("cp.async.commit_group;" ::: "memory");
    }
    __syncthreads();

    // ---- ||x||^2 per row ----
    if (tid < 32) {
        const float4* xr = (const float4*)&s_x[tid * XP];
        float s = 0.f;
        #pragma unroll
        for (int f = 0; f < 16; f++) {
            float4 v = xr[f];
            s = fmaf(v.x, v.x, s); s = fmaf(v.y, v.y, s);
            s = fmaf(v.z, v.z, s); s = fmaf(v.w, v.w, s);
        }
        s_xx[tid] = s;
    }

    // ---- phase 1: 8 passes x 64 centers, double-buffered; store rbf TRANSPOSED ----
    int buf = 0;
    for (int p = 0; p < 8; p++) {
        if (p < 7) {
            const float4* src = (const float4*)(centers + (p + 1) * 64 * FIN);
            int nb = buf ^ 1;
            #pragma unroll
            for (int i = tid; i < 1024; i += NTHR) {
                int r = i >> 4, c = i & 15;
                cp16(smem_u + (SM_U + nb * 64 * XP + r * XP + c * 4) * 4, src + i);
            }
            asm volatile("cp.async.commit_group;" ::: "memory");
            asm volatile("cp.async.wait_group 1;" ::: "memory");
        } else {
            asm volatile("cp.async.wait_group 0;" ::: "memory");
        }
        __syncthreads();

        const float* cb = sm + SM_U + buf * 64 * XP + (warp * 4) * XP;
        const float* xp = &s_x[lane * XP];
        unsigned long long a0 = 0, a1 = 0, a2 = 0, a3 = 0;
        #pragma unroll
        for (int fc = 0; fc < 16; fc++) {
            ulonglong2 xv = *(const ulonglong2*)(xp + fc * 4);
            ulonglong2 c0 = *(const ulonglong2*)(cb + 0 * XP + fc * 4);
            ulonglong2 c1 = *(const ulonglong2*)(cb + 1 * XP + fc * 4);
            ulonglong2 c2 = *(const ulonglong2*)(cb + 2 * XP + fc * 4);
            ulonglong2 c3 = *(const ulonglong2*)(cb + 3 * XP + fc * 4);
            FMA2(a0, xv.x, c0.x); FMA2(a0, xv.y, c0.y);
            FMA2(a1, xv.x, c1.x); FMA2(a1, xv.y, c1.y);
            FMA2(a2, xv.x, c2.x); FMA2(a2, xv.y, c2.y);
            FMA2(a3, xv.x, c3.x); FMA2(a3, xv.y, c3.y);
        }
        const int kg = p * 64 + warp * 4;
        const float xxr = s_xx[lane];
        float* rrow = s_rbf + lane * PR;      // transposed: [row][k], conflict-free STS.32
        {
            float lo, hi, r2;
            asm("mov.b64 {%0,%1}, %2;" : "=f"(lo), "=f"(hi) : "l"(a0));
            r2 = fmaf(-2.f, lo + hi, xxr + s_cc[kg + 0]);
            rrow[kg + 0] = __expf(-s_s2[kg + 0] * r2);
            asm("mov.b64 {%0,%1}, %2;" : "=f"(lo), "=f"(hi) : "l"(a1));
            r2 = fmaf(-2.f, lo + hi, xxr + s_cc[kg + 1]);
            rrow[kg + 1] = __expf(-s_s2[kg + 1] * r2);
            asm("mov.b64 {%0,%1}, %2;" : "=f"(lo), "=f"(hi) : "l"(a2));
            r2 = fmaf(-2.f, lo + hi, xxr + s_cc[kg + 2]);
            rrow[kg + 2] = __expf(-s_s2[kg + 2] * r2);
            asm("mov.b64 {%0,%1}, %2;" : "=f"(lo), "=f"(hi) : "l"(a3));
            r2 = fmaf(-2.f, lo + hi, xxr + s_cc[kg + 3]);
            rrow[kg + 3] = __expf(-s_s2[kg + 3] * r2);
        }
        __syncthreads();
        buf ^= 1;
    }

    // ---- issue W chunks 0 and 1 (overlap with phase 2) ----
    #pragma unroll
    for (int ch = 0; ch < 2; ch++) {
        const float* src = W + ch * KC;
        #pragma unroll
        for (int i = tid; i < FOUT * (KC / 4); i += NTHR) {   // 4096 float4
            int o = i >> 4, c = i & 15;
            cp16(smem_u + (SM_U + ch * FOUT * WP + o * WP + c * 4) * 4,
                 src + (size_t)o * NK + c * 4);
        }
        asm volatile("cp.async.commit_group;" ::: "memory");
    }

    // ---- phase 2: row sums -> 1/(1e-9+sum); warp handles rows {warp, warp+16} ----
    #pragma unroll
    for (int rr = 0; rr < 2; rr++) {
        int row = warp + rr * 16;
        const float4* rp4 = (const float4*)(s_rbf + row * PR + lane * 16);
        float4 v0 = rp4[0], v1 = rp4[1], v2 = rp4[2], v3 = rp4[3];
        float s = ((v0.x + v0.y) + (v0.z + v0.w)) + ((v1.x + v1.y) + (v1.z + v1.w))
                + ((v2.x + v2.y) + (v2.z + v2.w)) + ((v3.x + v3.y) + (v3.z + v3.w));
        #pragma unroll
        for (int off = 16; off; off >>= 1) s += __shfl_xor_sync(0xffffffffu, s, off);
        if (lane == 0) s_inv[row] = 1.f / (1e-9f + s);
    }

    // ---- phase 3: out = (rbf @ W^T) * inv ----
    // warp -> 16 cols [warp*16, +16); lane: rows (lane&7)*4..+3, cols +(lane>>3)*4..+3
    const int r0 = (lane & 7) * 4;
    const int c0 = warp * 16 + (lane >> 3) * 4;
    const float* rp = s_rbf + r0 * PR;

    unsigned long long acc[4][4];
    #pragma unroll
    for (int r = 0; r < 4; r++)
        #pragma unroll
        for (int c = 0; c < 4; c++) acc[r][c] = 0ULL;

    for (int p = 0; p < NCH; p++) {
        if (p < NCH - 1) asm volatile("cp.async.wait_group 1;" ::: "memory");
        else             asm volatile("cp.async.wait_group 0;" ::: "memory");
        __syncthreads();

        const float* wb = sm + SM_U + (p & 1) * FOUT * WP + c0 * WP;
        #pragma unroll
        for (int kl = 0; kl < KC; kl += 4) {
            const int kg = p * KC + kl;
            ulonglong2 rv0 = *(const ulonglong2*)(rp + 0 * PR + kg);
            ulonglong2 rv1 = *(const ulonglong2*)(rp + 1 * PR + kg);
            ulonglong2 rv2 = *(const ulonglong2*)(rp + 2 * PR + kg);
            ulonglong2 rv3 = *(const ulonglong2*)(rp + 3 * PR + kg);
            ulonglong2 wv0 = *(const ulonglong2*)(wb + 0 * WP + kl);
            ulonglong2 wv1 = *(const ulonglong2*)(wb + 1 * WP + kl);
            ulonglong2 wv2 = *(const ulonglong2*)(wb + 2 * WP + kl);
            ulonglong2 wv3 = *(const ulonglong2*)(wb + 3 * WP + kl);
            FMA2(acc[0][0], rv0.x, wv0.x); FMA2(acc[0][0], rv0.y, wv0.y);
            FMA2(acc[0][1], rv0.x, wv1.x); FMA2(acc[0][1], rv0.y, wv1.y);
            FMA2(acc[0][2], rv0.x, wv2.x); FMA2(acc[0][2], rv0.y, wv2.y);
            FMA2(acc[0][3], rv0.x, wv3.x); FMA2(acc[0][3], rv0.y, wv3.y);
            FMA2(acc[1][0], rv1.x, wv0.x); FMA2(acc[1][0], rv1.y, wv0.y);
            FMA2(acc[1][1], rv1.x, wv1.x); FMA2(acc[1][1], rv1.y, wv1.y);
            FMA2(acc[1][2], rv1.x, wv2.x); FMA2(acc[1][2], rv1.y, wv2.y);
            FMA2(acc[1][3], rv1.x, wv3.x); FMA2(acc[1][3], rv1.y, wv3.y);
            FMA2(acc[2][0], rv2.x, wv0.x); FMA2(acc[2][0], rv2.y, wv0.y);
            FMA2(acc[2][1], rv2.x, wv1.x); FMA2(acc[2][1], rv2.y, wv1.y);
            FMA2(acc[2][2], rv2.x, wv2.x); FMA2(acc[2][2], rv2.y, wv2.y);
            FMA2(acc[2][3], rv2.x, wv3.x); FMA2(acc[2][3], rv2.y, wv3.y);
            FMA2(acc[3][0], rv3.x, wv0.x); FMA2(acc[3][0], rv3.y, wv0.y);
            FMA2(acc[3][1], rv3.x, wv1.x); FMA2(acc[3][1], rv3.y, wv1.y);
            FMA2(acc[3][2], rv3.x, wv2.x); FMA2(acc[3][2], rv3.y, wv2.y);
            FMA2(acc[3][3], rv3.x, wv3.x); FMA2(acc[3][3], rv3.y, wv3.y);
        }
        __syncthreads();    // all reads of buf (p&1) done before refill

        if (p + 2 < NCH) {
            const float* src = W + (p + 2) * KC;
            #pragma unroll
            for (int i = tid; i < FOUT * (KC / 4); i += NTHR) {
                int o = i >> 4, c = i & 15;
                cp16(smem_u + (SM_U + (p & 1) * FOUT * WP + o * WP + c * 4) * 4,
                     src + (size_t)o * NK + c * 4);
            }
            asm volatile("cp.async.commit_group;" ::: "memory");
        }
    }

    // ---- epilogue: horizontal add, normalize, store float4 ----
    #pragma unroll
    for (int r = 0; r < 4; r++) {
        const float inv = s_inv[r0 + r];
        float4 o4;
        float lo, hi;
        asm("mov.b64 {%0,%1}, %2;" : "=f"(lo), "=f"(hi) : "l"(acc[r][0]));
        o4.x = (lo + hi) * inv;
        asm("mov.b64 {%0,%1}, %2;" : "=f"(lo), "=f"(hi) : "l"(acc[r][1]));
        o4.y = (lo + hi) * inv;
        asm("mov.b64 {%0,%1}, %2;" : "=f"(lo), "=f"(hi) : "l"(acc[r][2]));
        o4.z = (lo + hi) * inv;
        asm("mov.b64 {%0,%1}, %2;" : "=f"(lo), "=f"(hi) : "l"(acc[r][3]));
        o4.w = (lo + hi) * inv;
        *(float4*)(out + (size_t)(b0 + r0 + r) * FOUT + c0) = o4;
    }
}

// -------- launch --------
extern "C" void kernel_launch(void* const* d_in, const int* in_sizes, int n_in,
                              void* d_out, int out_size) {
    const float* x       = (const float*)d_in[0];  // [4096, 64]
    const float* W       = (const float*)d_in[1];  // [256, 512]
    const float* centers = (const float*)d_in[2];  // [512, 64]
    const float* ls      = (const float*)d_in[3];  // [512]
    float* out = (float*)d_out;                    // [4096, 256]

    cudaFuncSetAttribute(rbf_main, cudaFuncAttributeMaxDynamicSharedMemorySize, SMEM_BYTES);

    prep_centers<<<16, 256>>>(centers, ls);
    rbf_main<<<B_ / TB, NTHR, SMEM_BYTES>>>(x, centers, W, out);
}

// round 5
// speedup vs baseline: 1.9454x; 1.9454x over previous
#include <cuda_runtime.h>
#include <cstdint>

#define B_    4096
#define FIN   64
#define NK    512
#define FOUT  256
#define TB    32
#define NTHR  512
#define XP    68            // x/center staging pitch
#define NCH   8             // W chunks of 64 k

typedef unsigned long long ull;

__device__ float g_cc[NK];            // ||c_k||^2
__device__ float g_s2[NK];            // exp(2*log_shape)
__device__ float g_Wb[NK * FOUT];     // k-pair blocked: [ch][kp][col][2]

// ---- smem layout (float offsets) ----
#define SM_RBF  0                          // [256 kp][32 rows][2] = 16384
#define SM_X    (SM_RBF + 16384)           // [32][XP]
#define SM_W0   (SM_X + TB*XP)             // W even-chunk buf: 16384
#define SM_U    (SM_W0 + 16384)            // union: W odd-chunk buf (16384) | centers 2*64*XP
#define SM_CC   (SM_U + 16384)
#define SM_S2   (SM_CC + NK)
#define SM_XX   (SM_S2 + NK)
#define SM_INV  (SM_XX + TB)
#define SM_PART (SM_INV + TB)              // [16][32]
#define SM_TOT  (SM_PART + 512)
#define SMEM_BYTES (SM_TOT * 4)            // ~207 KB

#define FMA2(a,b,c) asm("fma.rn.f32x2 %0, %1, %2, %0;" : "+l"(a) : "l"(b), "l"(c))
#define UNPK(lo,hi,v) asm("mov.b64 {%0,%1}, %2;" : "=f"(lo), "=f"(hi) : "l"(v))

__device__ __forceinline__ void cp16(uint32_t dst, const void* src) {
    asm volatile("cp.async.ca.shared.global [%0], [%1], 16;" :: "r"(dst), "l"(src));
}
#define CP_COMMIT() asm volatile("cp.async.commit_group;" ::: "memory")
#define CP_WAIT(n)  asm volatile("cp.async.wait_group %0;" :: "n"(n) : "memory")

// -------- prep: ||c||^2, exp(2 ls), and W k-pair repack --------
__global__ void prep_all(const float* __restrict__ W,
                         const float* __restrict__ centers,
                         const float* __restrict__ ls) {
    int bid = blockIdx.x;
    if (bid < 16) {
        int kb = bid * 32;
        int warp = threadIdx.x >> 5, lane = threadIdx.x & 31;
        #pragma unroll
        for (int c = warp; c < 32; c += 8) {
            int k = kb + c;
            float v0 = centers[k * FIN + lane];
            float v1 = centers[k * FIN + 32 + lane];
            float s = fmaf(v0, v0, v1 * v1);
            #pragma unroll
            for (int off = 16; off; off >>= 1) s += __shfl_xor_sync(0xffffffffu, s, off);
            if (lane == 0) g_cc[k] = s;
        }
        if (threadIdx.x < 32) g_s2[kb + threadIdx.x] = __expf(2.f * ls[kb + threadIdx.x]);
    } else {
        // W pack: g_Wb float4 t = {W[c][k],W[c][k+1],W[c+1][k],W[c+1][k+1]}
        int t   = (bid - 16) * 256 + threadIdx.x;    // 0..32767
        int ch  = t >> 12;
        int rem = t & 4095;
        int kp  = rem >> 7;
        int c   = (rem & 127) * 2;
        int kb  = ch * 64 + kp * 2;
        float2 a = *(const float2*)(W + (size_t)c * NK + kb);
        float2 b = *(const float2*)(W + (size_t)(c + 1) * NK + kb);
        ((float4*)g_Wb)[t] = make_float4(a.x, a.y, b.x, b.y);
    }
}

// -------- fused main kernel --------
__global__ __launch_bounds__(NTHR, 1)
void rbf_main(const float* __restrict__ x,
              const float* __restrict__ centers,
              float* __restrict__ out) {
    extern __shared__ float sm[];
    const int tid  = threadIdx.x;
    const int lane = tid & 31;
    const int warp = tid >> 5;
    const int b0   = blockIdx.x * TB;
    const uint32_t smem_u = (uint32_t)__cvta_generic_to_shared(sm);

    // ---- stage x tile + per-k constants ----
    {
        const float4* x4 = (const float4*)(x + (size_t)b0 * FIN);
        int r = tid >> 4, c = tid & 15;
        *(float4*)&sm[SM_X + r * XP + c * 4] = x4[r * 16 + c];
        sm[SM_CC + tid] = g_cc[tid];
        sm[SM_S2 + tid] = g_s2[tid];
    }
    // ---- cp.async: W chunk 0 (loads during all of phase 1) ----
    {
        const float4* src = (const float4*)g_Wb;
        #pragma unroll
        for (int i = tid; i < 4096; i += NTHR) cp16(smem_u + (SM_W0 + i * 4) * 4, src + i);
        CP_COMMIT();
    }
    // ---- cp.async: center pass 0 into union buf 0 ----
    {
        const float4* src = (const float4*)centers;
        #pragma unroll
        for (int i = tid; i < 1024; i += NTHR) {
            int r = i >> 4, c = i & 15;
            cp16(smem_u + (SM_U + r * XP + c * 4) * 4, src + i);
        }
        CP_COMMIT();
    }
    __syncthreads();

    // ---- ||x||^2 per row ----
    if (tid < 32) {
        const float4* xr4 = (const float4*)&sm[SM_X + tid * XP];
        float s = 0.f;
        #pragma unroll
        for (int f = 0; f < 16; f++) {
            float4 v = xr4[f];
            s = fmaf(v.x, v.x, s); s = fmaf(v.y, v.y, s);
            s = fmaf(v.z, v.z, s); s = fmaf(v.w, v.w, s);
        }
        sm[SM_XX + tid] = s;
    }

    // ---- hoist this lane's x row (64 floats) into registers ----
    ull xr[32];
    {
        const float* xp = sm + SM_X + lane * XP;
        #pragma unroll
        for (int f = 0; f < 16; f++) {
            ulonglong2 t2 = *(const ulonglong2*)(xp + f * 4);
            xr[2 * f] = t2.x; xr[2 * f + 1] = t2.y;
        }
    }

    // ---- phase 1: 8 passes x 64 centers; rbf stored k-pair-blocked; psum folded ----
    float psum = 0.f;
    int buf = 0;
    for (int p = 0; p < 8; p++) {
        if (p < 7) {
            const float4* src = (const float4*)(centers + (p + 1) * 64 * FIN);
            int nb = buf ^ 1;
            #pragma unroll
            for (int i = tid; i < 1024; i += NTHR) {
                int r = i >> 4, c = i & 15;
                cp16(smem_u + (SM_U + nb * 64 * XP + r * XP + c * 4) * 4, src + i);
            }
            CP_COMMIT();
            CP_WAIT(1);
        } else {
            CP_WAIT(0);
        }
        __syncthreads();

        const float* cb = sm + SM_U + buf * 64 * XP + (warp * 4) * XP;
        ull a0 = 0, a1 = 0, a2 = 0, a3 = 0;
        #pragma unroll
        for (int f = 0; f < 16; f++) {
            ulonglong2 c0v = *(const ulonglong2*)(cb + 0 * XP + f * 4);
            ulonglong2 c1v = *(const ulonglong2*)(cb + 1 * XP + f * 4);
            ulonglong2 c2v = *(const ulonglong2*)(cb + 2 * XP + f * 4);
            ulonglong2 c3v = *(const ulonglong2*)(cb + 3 * XP + f * 4);
            FMA2(a0, xr[2*f], c0v.x); FMA2(a0, xr[2*f+1], c0v.y);
            FMA2(a1, xr[2*f], c1v.x); FMA2(a1, xr[2*f+1], c1v.y);
            FMA2(a2, xr[2*f], c2v.x); FMA2(a2, xr[2*f+1], c2v.y);
            FMA2(a3, xr[2*f], c3v.x); FMA2(a3, xr[2*f+1], c3v.y);
        }
        const int kg = p * 64 + warp * 4;
        const float xxr = sm[SM_XX + lane];
        float lo, hi, r2, v0, v1, v2, v3;
        UNPK(lo, hi, a0); r2 = fmaf(-2.f, lo + hi, xxr + sm[SM_CC + kg + 0]);
        v0 = __expf(-sm[SM_S2 + kg + 0] * r2);
        UNPK(lo, hi, a1); r2 = fmaf(-2.f, lo + hi, xxr + sm[SM_CC + kg + 1]);
        v1 = __expf(-sm[SM_S2 + kg + 1] * r2);
        UNPK(lo, hi, a2); r2 = fmaf(-2.f, lo + hi, xxr + sm[SM_CC + kg + 2]);
        v2 = __expf(-sm[SM_S2 + kg + 2] * r2);
        UNPK(lo, hi, a3); r2 = fmaf(-2.f, lo + hi, xxr + sm[SM_CC + kg + 3]);
        v3 = __expf(-sm[SM_S2 + kg + 3] * r2);
        psum += (v0 + v1) + (v2 + v3);

        float* dst = sm + SM_RBF + (kg >> 1) * 64 + lane * 2;   // [kp][row][2]
        *(float2*)dst        = make_float2(v0, v1);
        *(float2*)(dst + 64) = make_float2(v2, v3);
        __syncthreads();
        buf ^= 1;
    }
    sm[SM_PART + warp * 32 + lane] = psum;

    // ---- cp.async: W chunk 1 into union buf (centers fully consumed) ----
    {
        const float4* src = (const float4*)g_Wb + 4096;
        #pragma unroll
        for (int i = tid; i < 4096; i += NTHR) cp16(smem_u + (SM_U + i * 4) * 4, src + i);
        CP_COMMIT();
    }
    __syncthreads();
    if (tid < 32) {
        float t = 1e-9f;
        #pragma unroll
        for (int w = 0; w < 16; w++) t += sm[SM_PART + w * 32 + tid];
        sm[SM_INV + tid] = 1.f / t;
    }

    // ---- phase 3: 4x4 thread tile, all-1-wavefront LDS ----
    const int g  = lane & 7;
    const int c0 = warp * 16 + (lane >> 3) * 4;
    ull acc[4][4];
    #pragma unroll
    for (int r = 0; r < 4; r++)
        #pragma unroll
        for (int c = 0; c < 4; c++) acc[r][c] = 0ULL;

    const float* rb0 = sm + SM_RBF + 4 * g;
    for (int p = 0; p < NCH; p++) {
        if (p < NCH - 1) CP_WAIT(1); else CP_WAIT(0);
        __syncthreads();

        const float* wbp = sm + (p & 1 ? SM_U : SM_W0) + c0 * 2;
        const float* rbp = rb0 + p * 2048;
        #pragma unroll
        for (int kp = 0; kp < 32; kp++) {
            ulonglong2 rlo = *(const ulonglong2*)(rbp + kp * 64);        // rows 2g,2g+1
            ulonglong2 rhi = *(const ulonglong2*)(rbp + kp * 64 + 32);   // rows 2g+16,2g+17
            ulonglong2 wa  = *(const ulonglong2*)(wbp + kp * 512);       // cols c0,c0+1
            ulonglong2 wb2 = *(const ulonglong2*)(wbp + kp * 512 + 4);   // cols c0+2,c0+3
            FMA2(acc[0][0], rlo.x, wa.x);  FMA2(acc[0][1], rlo.x, wa.y);
            FMA2(acc[0][2], rlo.x, wb2.x); FMA2(acc[0][3], rlo.x, wb2.y);
            FMA2(acc[1][0], rlo.y, wa.x);  FMA2(acc[1][1], rlo.y, wa.y);
            FMA2(acc[1][2], rlo.y, wb2.x); FMA2(acc[1][3], rlo.y, wb2.y);
            FMA2(acc[2][0], rhi.x, wa.x);  FMA2(acc[2][1], rhi.x, wa.y);
            FMA2(acc[2][2], rhi.x, wb2.x); FMA2(acc[2][3], rhi.x, wb2.y);
            FMA2(acc[3][0], rhi.y, wa.x);  FMA2(acc[3][1], rhi.y, wa.y);
            FMA2(acc[3][2], rhi.y, wb2.x); FMA2(acc[3][3], rhi.y, wb2.y);
        }
        __syncthreads();
        if (p + 2 < NCH) {
            const float4* src = (const float4*)g_Wb + (p + 2) * 4096;
            const uint32_t db = smem_u + ((p & 1 ? SM_U : SM_W0)) * 4;
            #pragma unroll
            for (int i = tid; i < 4096; i += NTHR) cp16(db + i * 16, src + i);
            CP_COMMIT();
        }
    }

    // ---- epilogue: horizontal add, normalize, store ----
    const int rows[4] = {2*g, 2*g + 1, 2*g + 16, 2*g + 17};
    #pragma unroll
    for (int r = 0; r < 4; r++) {
        const float inv = sm[SM_INV + rows[r]];
        float lo, hi;
        float4 o4;
        UNPK(lo, hi, acc[r][0]); o4.x = (lo + hi) * inv;
        UNPK(lo, hi, acc[r][1]); o4.y = (lo + hi) * inv;
        UNPK(lo, hi, acc[r][2]); o4.z = (lo + hi) * inv;
        UNPK(lo, hi, acc[r][3]); o4.w = (lo + hi) * inv;
        *(float4*)(out + (size_t)(b0 + rows[r]) * FOUT + c0) = o4;
    }
}

// -------- launch --------
extern "C" void kernel_launch(void* const* d_in, const int* in_sizes, int n_in,
                              void* d_out, int out_size) {
    const float* x       = (const float*)d_in[0];  // [4096, 64]
    const float* W       = (const float*)d_in[1];  // [256, 512]
    const float* centers = (const float*)d_in[2];  // [512, 64]
    const float* ls      = (const float*)d_in[3];  // [512]
    float* out = (float*)d_out;                    // [4096, 256]

    cudaFuncSetAttribute(rbf_main, cudaFuncAttributeMaxDynamicSharedMemorySize, SMEM_BYTES);

    prep_all<<<144, 256>>>(W, centers, ls);
    rbf_main<<<B_ / TB, NTHR, SMEM_BYTES>>>(x, centers, out);
}

// round 7
// speedup vs baseline: 2.6028x; 1.3379x over previous
#include <cuda_runtime.h>
#include <cuda_bf16.h>
#include <cstdint>

#define B_    4096
#define FIN   64
#define NK    512
#define FOUT  256
#define TB    32
#define NTHR  512
#define XP    68             // x/center staging pitch (floats)
#define AP    40             // A (rbf bf16x2) pitch in b32: conflict-free
#define BWP   24             // B pitch in b32 per kp row: conflict-free
#define NCHK  16             // 16 W chunks: 0-7 = W_hi, 8-15 = W_lo

typedef unsigned long long ull;

__device__ float    g_cc[NK];
__device__ float    g_s2[NK];
__device__ uint32_t g_Wpk[NCHK * 16 * 32 * BWP];   // [chunk][warp][kp][24] bf16x2

// ---- smem layout (float offsets) ----
#define SM_A    0                      // rbf bf16x2: [512 kp_eff][40] b32 = 20480
#define SM_B0   20480                  // W chunk buf 0: 12288 b32
#define SM_B1   32768                  // W chunk buf 1 (union: phase-1 centers 2*64*XP)
#define SM_X    45056                  // [32][XP]
#define SM_CC   (SM_X + TB*XP)
#define SM_S2   (SM_CC + NK)
#define SM_XX   (SM_S2 + NK)
#define SM_INV  (SM_XX + TB)
#define SM_PART (SM_INV + TB)          // [16][32]
#define SM_TOT  (SM_PART + 512)
#define SMEM_BYTES (SM_TOT * 4)        // ~195 KB

#define FMA2(a,b,c) asm("fma.rn.f32x2 %0, %1, %2, %0;" : "+l"(a) : "l"(b), "l"(c))
#define UNPK(lo,hi,v) asm("mov.b64 {%0,%1}, %2;" : "=f"(lo), "=f"(hi) : "l"(v))

__device__ __forceinline__ void cp16(uint32_t dst, const void* src) {
    asm volatile("cp.async.ca.shared.global [%0], [%1], 16;" :: "r"(dst), "l"(src));
}
#define CP_COMMIT() asm volatile("cp.async.commit_group;" ::: "memory")
#define CP_WAIT(n)  asm volatile("cp.async.wait_group %0;" :: "n"(n) : "memory")

__device__ __forceinline__ uint32_t pack_bf2(__nv_bfloat16 a, __nv_bfloat16 b) {
    __nv_bfloat162 t; t.x = a; t.y = b;
    return *reinterpret_cast<uint32_t*>(&t);
}

#define MMA16816(D,a0,a1,a2,a3,b0,b1) \
    asm("mma.sync.aligned.m16n8k16.row.col.f32.bf16.bf16.f32 " \
        "{%0,%1,%2,%3}, {%4,%5,%6,%7}, {%8,%9}, {%0,%1,%2,%3};" \
        : "+f"(D[0]), "+f"(D[1]), "+f"(D[2]), "+f"(D[3]) \
        : "r"(a0), "r"(a1), "r"(a2), "r"(a3), "r"(b0), "r"(b1))

// -------- prep: ||c||^2, exp(2 ls), and W split-bf16 fragment pack --------
__global__ void prep_all(const float* __restrict__ W,
                         const float* __restrict__ centers,
                         const float* __restrict__ ls) {
    int bid = blockIdx.x;
    if (bid < 16) {
        int kb = bid * 32;
        int warp = threadIdx.x >> 5, lane = threadIdx.x & 31;
        #pragma unroll
        for (int c = warp; c < 32; c += 8) {
            int k = kb + c;
            float v0 = centers[k * FIN + lane];
            float v1 = centers[k * FIN + 32 + lane];
            float s = fmaf(v0, v0, v1 * v1);
            #pragma unroll
            for (int off = 16; off; off >>= 1) s += __shfl_xor_sync(0xffffffffu, s, off);
            if (lane == 0) g_cc[k] = s;
        }
        if (threadIdx.x < 32) g_s2[kb + threadIdx.x] = __expf(2.f * ls[kb + threadIdx.x]);
    } else {
        // chunks 0-7: W_hi(k 0..511); chunks 8-15: W_lo(k 0..511)
        int idx = (bid - 16) * 256 + threadIdx.x;    // 0..131071
        int c  = idx & 15;
        int kp = (idx >> 4) & 31;
        int w  = (idx >> 9) & 15;
        int h  = idx >> 13;                          // 0..15
        int split = h >> 3;                          // 0 = hi, 1 = lo
        int k  = ((h & 7) * 64 + kp * 2);
        int col = w * 16 + c;
        float w0 = W[(size_t)col * NK + k];
        float w1 = W[(size_t)col * NK + k + 1];
        __nv_bfloat16 h0 = __float2bfloat16(w0);
        __nv_bfloat16 h1 = __float2bfloat16(w1);
        __nv_bfloat16 v0 = split ? __float2bfloat16(w0 - __bfloat162float(h0)) : h0;
        __nv_bfloat16 v1 = split ? __float2bfloat16(w1 - __bfloat162float(h1)) : h1;
        g_Wpk[((h * 16 + w) * 32 + kp) * BWP + c] = pack_bf2(v0, v1);
    }
}

// -------- fused main kernel --------
__global__ __launch_bounds__(NTHR, 1)
void rbf_main(const float* __restrict__ x,
              const float* __restrict__ centers,
              float* __restrict__ out) {
    extern __shared__ float sm[];
    const int tid  = threadIdx.x;
    const int lane = tid & 31;
    const int warp = tid >> 5;
    const int b0   = blockIdx.x * TB;
    const uint32_t smem_u = (uint32_t)__cvta_generic_to_shared(sm);
    uint32_t* A32 = (uint32_t*)(sm + SM_A);

    // ---- stage x tile + per-k constants ----
    {
        const float4* x4 = (const float4*)(x + (size_t)b0 * FIN);
        int r = tid >> 4, c = tid & 15;
        *(float4*)&sm[SM_X + r * XP + c * 4] = x4[r * 16 + c];
        sm[SM_CC + tid] = g_cc[tid];
        sm[SM_S2 + tid] = g_s2[tid];
    }
    // ---- group 0: W chunk 0 into B0 + center pass 0 into B1 buf0 ----
    {
        const float4* wsrc = (const float4*)g_Wpk;
        #pragma unroll
        for (int i = tid; i < 3072; i += NTHR) cp16(smem_u + SM_B0 * 4 + i * 16, wsrc + i);
        const float4* csrc = (const float4*)centers;
        #pragma unroll
        for (int i = tid; i < 1024; i += NTHR) {
            int r = i >> 4, c = i & 15;
            cp16(smem_u + (SM_B1 + r * XP + c * 4) * 4, csrc + i);
        }
        CP_COMMIT();
    }
    __syncthreads();

    // ---- ||x||^2 per row ----
    if (tid < 32) {
        const float4* xr4 = (const float4*)&sm[SM_X + tid * XP];
        float s = 0.f;
        #pragma unroll
        for (int f = 0; f < 16; f++) {
            float4 v = xr4[f];
            s = fmaf(v.x, v.x, s); s = fmaf(v.y, v.y, s);
            s = fmaf(v.z, v.z, s); s = fmaf(v.w, v.w, s);
        }
        sm[SM_XX + tid] = s;
    }

    // ---- hoist lane's x row into registers ----
    ull xr[32];
    {
        const float* xp = sm + SM_X + lane * XP;
        #pragma unroll
        for (int f = 0; f < 16; f++) {
            ulonglong2 t2 = *(const ulonglong2*)(xp + f * 4);
            xr[2 * f] = t2.x; xr[2 * f + 1] = t2.y;
        }
    }

    // ---- phase 1: 8 passes x 64 centers; rbf -> split-bf16 fragment layout ----
    float psum = 0.f;
    int buf = 0;
    for (int p = 0; p < 8; p++) {
        if (p < 7) {
            const float4* src = (const float4*)(centers + (p + 1) * 64 * FIN);
            int nb = buf ^ 1;
            #pragma unroll
            for (int i = tid; i < 1024; i += NTHR) {
                int r = i >> 4, c = i & 15;
                cp16(smem_u + (SM_B1 + nb * 64 * XP + r * XP + c * 4) * 4, src + i);
            }
            CP_COMMIT();
            CP_WAIT(1);
        } else {
            CP_WAIT(0);
        }
        __syncthreads();

        const float* cb = sm + SM_B1 + buf * 64 * XP + (warp * 4) * XP;
        ull a0 = 0, a1 = 0, a2 = 0, a3 = 0;
        #pragma unroll
        for (int f = 0; f < 16; f++) {
            ulonglong2 c0v = *(const ulonglong2*)(cb + 0 * XP + f * 4);
            ulonglong2 c1v = *(const ulonglong2*)(cb + 1 * XP + f * 4);
            ulonglong2 c2v = *(const ulonglong2*)(cb + 2 * XP + f * 4);
            ulonglong2 c3v = *(const ulonglong2*)(cb + 3 * XP + f * 4);
            FMA2(a0, xr[2*f], c0v.x); FMA2(a0, xr[2*f+1], c0v.y);
            FMA2(a1, xr[2*f], c1v.x); FMA2(a1, xr[2*f+1], c1v.y);
            FMA2(a2, xr[2*f], c2v.x); FMA2(a2, xr[2*f+1], c2v.y);
            FMA2(a3, xr[2*f], c3v.x); FMA2(a3, xr[2*f+1], c3v.y);
        }
        const int kg = p * 64 + warp * 4;
        const float xxr = sm[SM_XX + lane];
        float lo, hi, r2, v0, v1, v2, v3;
        UNPK(lo, hi, a0); r2 = fmaf(-2.f, lo + hi, xxr + sm[SM_CC + kg + 0]);
        v0 = __expf(-sm[SM_S2 + kg + 0] * r2);
        UNPK(lo, hi, a1); r2 = fmaf(-2.f, lo + hi, xxr + sm[SM_CC + kg + 1]);
        v1 = __expf(-sm[SM_S2 + kg + 1] * r2);
        UNPK(lo, hi, a2); r2 = fmaf(-2.f, lo + hi, xxr + sm[SM_CC + kg + 2]);
        v2 = __expf(-sm[SM_S2 + kg + 2] * r2);
        UNPK(lo, hi, a3); r2 = fmaf(-2.f, lo + hi, xxr + sm[SM_CC + kg + 3]);
        v3 = __expf(-sm[SM_S2 + kg + 3] * r2);
        psum += (v0 + v1) + (v2 + v3);

        // split-bf16 store: kp 0..255 = R_hi, 256..511 = R_lo
        __nv_bfloat16 h0 = __float2bfloat16(v0), h1 = __float2bfloat16(v1);
        __nv_bfloat16 h2 = __float2bfloat16(v2), h3 = __float2bfloat16(v3);
        __nv_bfloat16 l0 = __float2bfloat16(v0 - __bfloat162float(h0));
        __nv_bfloat16 l1 = __float2bfloat16(v1 - __bfloat162float(h1));
        __nv_bfloat16 l2 = __float2bfloat16(v2 - __bfloat162float(h2));
        __nv_bfloat16 l3 = __float2bfloat16(v3 - __bfloat162float(h3));
        const int kp = kg >> 1;
        A32[(kp    ) * AP + lane] = pack_bf2(h0, h1);
        A32[(kp + 1) * AP + lane] = pack_bf2(h2, h3);
        A32[(256 + kp    ) * AP + lane] = pack_bf2(l0, l1);
        A32[(256 + kp + 1) * AP + lane] = pack_bf2(l2, l3);
        __syncthreads();
        buf ^= 1;
    }
    sm[SM_PART + warp * 32 + lane] = psum;

    // ---- W chunk 1 into B1 (centers consumed) ----
    {
        const float4* src = (const float4*)g_Wpk + 3072;
        #pragma unroll
        for (int i = tid; i < 3072; i += NTHR) cp16(smem_u + SM_B1 * 4 + i * 16, src + i);
        CP_COMMIT();
    }
    __syncthreads();
    if (tid < 32) {
        float t = 1e-9f;
        #pragma unroll
        for (int w = 0; w < 16; w++) t += sm[SM_PART + w * 32 + tid];
        sm[SM_INV + tid] = 1.f / t;
    }

    // ---- phase 3: tensor GEMM. D = R_hi*(W_hi+W_lo) + R_lo*W_hi ----
    const int g   = lane >> 2;       // groupID 0..7
    const int tig = lane & 3;        // thread-in-group
    float acc[2][2][4];
    #pragma unroll
    for (int mt = 0; mt < 2; mt++)
        #pragma unroll
        for (int nt = 0; nt < 2; nt++)
            #pragma unroll
            for (int i = 0; i < 4; i++) acc[mt][nt][i] = 0.f;

    const uint32_t* B0p = (const uint32_t*)(sm + SM_B0) + warp * (32 * BWP);
    const uint32_t* B1p = (const uint32_t*)(sm + SM_B1) + warp * (32 * BWP);

    for (int h = 0; h < NCHK; h++) {
        if (h < NCHK - 1) CP_WAIT(1); else CP_WAIT(0);
        __syncthreads();
        const uint32_t* Bp = (h & 1) ? B1p : B0p;
        const int hiBase = (h & 7) * 32;   // R_hi kp region for this chunk's k range
        #pragma unroll
        for (int ks = 0; ks < 4; ks++) {
            const int kpA = hiBase + ks * 8 + tig;
            // B fragments for this warp's 16-col strip
            uint32_t b00 = Bp[(ks * 8 + tig    ) * BWP + g];
            uint32_t b01 = Bp[(ks * 8 + tig + 4) * BWP + g];
            uint32_t b10 = Bp[(ks * 8 + tig    ) * BWP + g + 8];
            uint32_t b11 = Bp[(ks * 8 + tig + 4) * BWP + g + 8];
            // A: R_hi fragments (always used)
            uint32_t a00 = A32[(kpA    ) * AP + g];
            uint32_t a01 = A32[(kpA    ) * AP + g + 8];
            uint32_t a02 = A32[(kpA + 4) * AP + g];
            uint32_t a03 = A32[(kpA + 4) * AP + g + 8];
            uint32_t a10 = A32[(kpA    ) * AP + g + 16];
            uint32_t a11 = A32[(kpA    ) * AP + g + 24];
            uint32_t a12 = A32[(kpA + 4) * AP + g + 16];
            uint32_t a13 = A32[(kpA + 4) * AP + g + 24];
            MMA16816(acc[0][0], a00, a01, a02, a03, b00, b01);
            MMA16816(acc[0][1], a00, a01, a02, a03, b10, b11);
            MMA16816(acc[1][0], a10, a11, a12, a13, b00, b01);
            MMA16816(acc[1][1], a10, a11, a12, a13, b10, b11);
            if (h < 8) {
                // W_hi chunk: also accumulate R_lo * W_hi
                const int kpL = kpA + 256;
                uint32_t c00 = A32[(kpL    ) * AP + g];
                uint32_t c01 = A32[(kpL    ) * AP + g + 8];
                uint32_t c02 = A32[(kpL + 4) * AP + g];
                uint32_t c03 = A32[(kpL + 4) * AP + g + 8];
                uint32_t c10 = A32[(kpL    ) * AP + g + 16];
                uint32_t c11 = A32[(kpL    ) * AP + g + 24];
                uint32_t c12 = A32[(kpL + 4) * AP + g + 16];
                uint32_t c13 = A32[(kpL + 4) * AP + g + 24];
                MMA16816(acc[0][0], c00, c01, c02, c03, b00, b01);
                MMA16816(acc[0][1], c00, c01, c02, c03, b10, b11);
                MMA16816(acc[1][0], c10, c11, c12, c13, b00, b01);
                MMA16816(acc[1][1], c10, c11, c12, c13, b10, b11);
            }
        }
        __syncthreads();     // all warps done reading buf (h&1) before refill
        if (h + 2 < NCHK) {
            const float4* src = (const float4*)g_Wpk + (h + 2) * 3072;
            const uint32_t db = smem_u + ((h & 1) ? SM_B1 : SM_B0) * 4;
            #pragma unroll
            for (int i = tid; i < 3072; i += NTHR) cp16(db + i * 16, src + i);
            CP_COMMIT();
        }
    }

    // ---- epilogue: normalize + store float2 per (mt,nt) half ----
    #pragma unroll
    for (int mt = 0; mt < 2; mt++) {
        #pragma unroll
        for (int nt = 0; nt < 2; nt++) {
            const int col = warp * 16 + nt * 8 + tig * 2;
            const int r0  = g + mt * 16;
            const int r1  = r0 + 8;
            const float i0 = sm[SM_INV + r0];
            const float i1 = sm[SM_INV + r1];
            *(float2*)(out + (size_t)(b0 + r0) * FOUT + col) =
                make_float2(acc[mt][nt][0] * i0, acc[mt][nt][1] * i0);
            *(float2*)(out + (size_t)(b0 + r1) * FOUT + col) =
                make_float2(acc[mt][nt][2] * i1, acc[mt][nt][3] * i1);
        }
    }
}

// -------- launch --------
extern "C" void kernel_launch(void* const* d_in, const int* in_sizes, int n_in,
                              void* d_out, int out_size) {
    const float* x       = (const float*)d_in[0];  // [4096, 64]
    const float* W       = (const float*)d_in[1];  // [256, 512]
    const float* centers = (const float*)d_in[2];  // [512, 64]
    const float* ls      = (const float*)d_in[3];  // [512]
    float* out = (float*)d_out;                    // [4096, 256]

    cudaFuncSetAttribute(rbf_main, cudaFuncAttributeMaxDynamicSharedMemorySize, SMEM_BYTES);

    prep_all<<<16 + 512, 256>>>(W, centers, ls);
    rbf_main<<<B_ / TB, NTHR, SMEM_BYTES>>>(x, centers, out);
}